// round 9
// baseline (speedup 1.0000x reference)
#include <cuda_runtime.h>

// RelativeAxialAttention, GB300.
// Pipeline:
//   zero_stats -> cov(x) -> fold BN into proj weights -> proj (kv+q, normalized)
//   -> attn pass1 (sim-BN variance stats, means cancel in softmax)
//   -> sim coeffs -> attn pass2 (softmax, sv/sve, out-BN stats)
//   -> out coeffs -> transpose+normalize+pair-sum write.

#define KH   48
#define BB   2304            // B = 48*48
#define NC   64              // CIN
#define NG   8               // G
#define NDK  8
#define NDV  16
#define NSP  110592.0        // B*KH   (proj & out BN sample count)
#define NSS  5308416.0       // B*KH*KH (sim BN sample count)
#define EPSV 1e-5f

// ---------------- scratch (static __device__, no allocs) ----------------
__device__ float d_S[64];
__device__ float d_P[64 * 64];
__device__ float d_Wt[64 * 256];        // folded weights, transposed [c][o]
__device__ float d_biasF[256];
__device__ float d_Pproj[BB * 256 * KH];          // [b][o][h], o: 0..191 kv, 192..255 q
__device__ float d_simstats[3 * NG * 2];          // [type*G+g][sum,sumsq]
__device__ float d_acoef[3 * NG];
__device__ float d_sv [NG * NDV * BB * KH];       // [g*16+c][b][i]
__device__ float d_sve[NG * NDV * BB * KH];
__device__ float d_outstats[128 * 4];             // [ch][sum_sv,sq_sv,sum_sve,sq_sve]
__device__ float d_outcoef[128 * 3];              // [ch][sc_sv, sc_sve, shift]

// ---------------- kernels ----------------
__global__ void zero_kernel() {
    int t = threadIdx.x;
    if (t < 64) d_S[t] = 0.f;
    for (int i = t; i < 4096; i += 512) d_P[i] = 0.f;
    if (t < 48)  d_simstats[t] = 0.f;
    d_outstats[t] = 0.f;   // 512 threads, 512 entries
}

// x channel sums + second-moment matrix over all 110592 positions.
__global__ __launch_bounds__(256) void cov_kernel(const float* __restrict__ x) {
    __shared__ float xs[64 * 97];
    const int tid = threadIdx.x;
    const int r = tid >> 4, cc = tid & 15;
    float acc[4][4];
#pragma unroll
    for (int i = 0; i < 4; i++)
#pragma unroll
        for (int j = 0; j < 4; j++) acc[i][j] = 0.f;
    float csum = 0.f;

    for (int t = blockIdx.x; t < 1152; t += gridDim.x) {
        const int p0 = t * 96;
        for (int idx = tid; idx < 64 * 96; idx += 256) {
            int ch = idx / 96, p = idx - ch * 96;
            xs[ch * 97 + p] = x[ch * 110592 + p0 + p];
        }
        __syncthreads();
        for (int p = 0; p < 96; p++) {
            float a0 = xs[(4 * r + 0) * 97 + p];
            float a1 = xs[(4 * r + 1) * 97 + p];
            float a2 = xs[(4 * r + 2) * 97 + p];
            float a3 = xs[(4 * r + 3) * 97 + p];
            float b0 = xs[(4 * cc + 0) * 97 + p];
            float b1 = xs[(4 * cc + 1) * 97 + p];
            float b2 = xs[(4 * cc + 2) * 97 + p];
            float b3 = xs[(4 * cc + 3) * 97 + p];
            acc[0][0] += a0 * b0; acc[0][1] += a0 * b1; acc[0][2] += a0 * b2; acc[0][3] += a0 * b3;
            acc[1][0] += a1 * b0; acc[1][1] += a1 * b1; acc[1][2] += a1 * b2; acc[1][3] += a1 * b3;
            acc[2][0] += a2 * b0; acc[2][1] += a2 * b1; acc[2][2] += a2 * b2; acc[2][3] += a2 * b3;
            acc[3][0] += a3 * b0; acc[3][1] += a3 * b1; acc[3][2] += a3 * b2; acc[3][3] += a3 * b3;
        }
        if (tid < 64) {
            float s = 0.f;
            for (int p = 0; p < 96; p++) s += xs[tid * 97 + p];
            csum += s;
        }
        __syncthreads();
    }
#pragma unroll
    for (int i = 0; i < 4; i++)
#pragma unroll
        for (int j = 0; j < 4; j++)
            atomicAdd(&d_P[(4 * r + i) * 64 + 4 * cc + j], acc[i][j]);
    if (tid < 64) atomicAdd(&d_S[tid], csum);
}

// Fold BN into projection weights. One block per output channel o (256 blocks, 64 threads).
__global__ void fold_kernel(const float* __restrict__ Wkv, const float* __restrict__ Wq,
                            const float* __restrict__ gkv, const float* __restrict__ bkv,
                            const float* __restrict__ gq,  const float* __restrict__ bq) {
    int o = blockIdx.x, d = threadIdx.x;
    __shared__ float ws[64], red[64], red2[64];
    __shared__ float sscale;
    float gg, bb;
    const float* Wrow;
    if (o < 192) { Wrow = Wkv + o * 64;        gg = gkv[o];       bb = bkv[o]; }
    else         { Wrow = Wq + (o - 192) * 64; gg = gq[o - 192];  bb = bq[o - 192]; }
    ws[d] = Wrow[d];
    __syncthreads();
    float mu_d = d_S[d] * (float)(1.0 / NSP);
    float col = 0.f;
    for (int c = 0; c < 64; c++) col += ws[c] * d_P[c * 64 + d];
    red[d]  = ws[d] * col;     // -> E[y^2] * NSP
    red2[d] = ws[d] * mu_d;    // -> mean
    __syncthreads();
    for (int s = 32; s > 0; s >>= 1) {
        if (d < s) { red[d] += red[d + s]; red2[d] += red2[d + s]; }
        __syncthreads();
    }
    if (d == 0) {
        float Ey2  = red[0] * (float)(1.0 / NSP);
        float mean = red2[0];
        float var  = Ey2 - mean * mean;
        float scale = gg * rsqrtf(var + EPSV);
        sscale = scale;
        d_biasF[o] = bb - mean * scale;
    }
    __syncthreads();
    d_Wt[d * 256 + o] = ws[d] * sscale;
}

// Projection: block per (w,h). Thread o computes 48 d-values (b = w*48+d).
__global__ __launch_bounds__(256) void proj_kernel(const float* __restrict__ x) {
    const int w = blockIdx.x / 48, h = blockIdx.x - (blockIdx.x / 48) * 48;
    const int o = threadIdx.x;
    __shared__ float4 xs[64 * 12];
    float W[64];
#pragma unroll
    for (int c = 0; c < 64; c++) W[c] = d_Wt[c * 256 + o];
    const float bias = d_biasF[o];
    const float* xb = x + h * 2304 + w * 48;
    float* xsf = (float*)xs;
    for (int idx = o; idx < 64 * 48; idx += 256) {
        int c = idx / 48, dd = idx - c * 48;
        xsf[c * 48 + dd] = xb[c * 110592 + dd];
    }
    __syncthreads();
#pragma unroll
    for (int dq = 0; dq < 12; dq++) {
        float4 acc = make_float4(bias, bias, bias, bias);
#pragma unroll
        for (int c = 0; c < 64; c++) {
            float wv = W[c];
            float4 xv = xs[c * 12 + dq];
            acc.x += wv * xv.x; acc.y += wv * xv.y;
            acc.z += wv * xv.z; acc.w += wv * xv.w;
        }
        const int d0 = dq * 4;
        const int base = ((w * 48 + d0) * 256 + o) * 48 + h;
        d_Pproj[base             ] = acc.x;
        d_Pproj[base + 256 * 48  ] = acc.y;
        d_Pproj[base + 2*256 * 48] = acc.z;
        d_Pproj[base + 3*256 * 48] = acc.w;
    }
}

// Attention pass 1: accumulate sim-BN sum/sumsq per (type,g) channel.
__global__ __launch_bounds__(256) void attn1_kernel(const float* __restrict__ rel,
                                                    const float* __restrict__ fqr_p,
                                                    const float* __restrict__ fkr_p) {
    const int b = blockIdx.x >> 3, g = blockIdx.x & 7;
    __shared__ float qs[384], ks[384], rq[8 * 96], rk[8 * 96];
    __shared__ float red[8][6];
    const int tid = threadIdx.x;
    const float* qsrc = d_Pproj + (b * 256 + 192 + g * 8) * 48;
    const float* ksrc = d_Pproj + (b * 256 + g * 24) * 48;
    for (int i = tid; i < 384; i += 256) { qs[i] = qsrc[i]; ks[i] = ksrc[i]; }
    for (int idx = tid; idx < 760; idx += 256) {
        int c = idx / 95, t = idx - c * 95;
        rq[c * 96 + t] = rel[idx];
        rk[c * 96 + t] = rel[760 + idx];
    }
    const float fqr = *fqr_p, fkr = *fkr_p;
    __syncthreads();

    float s[6] = {0.f, 0.f, 0.f, 0.f, 0.f, 0.f};
    for (int m = 0; m < 9; m++) {
        int idx = tid + m * 256;
        int i = idx / 48, j = idx - i * 48;
        int tq = i - j + 47, tk = j - i + 47;
        float qk = 0.f, qr = 0.f, kr = 0.f;
#pragma unroll
        for (int c = 0; c < 8; c++) {
            float qv = qs[c * 48 + i], kv = ks[c * 48 + j];
            qk += qv * kv;
            qr += qv * rq[c * 96 + tq];
            kr += kv * rk[c * 96 + tk];
        }
        qr *= fqr; kr *= fkr;
        s[0] += qk; s[1] += qk * qk;
        s[2] += qr; s[3] += qr * qr;
        s[4] += kr; s[5] += kr * kr;
    }
#pragma unroll
    for (int off = 16; off; off >>= 1)
#pragma unroll
        for (int k = 0; k < 6; k++) s[k] += __shfl_xor_sync(0xffffffffu, s[k], off);
    const int wid = tid >> 5, lane = tid & 31;
    if (lane == 0)
#pragma unroll
        for (int k = 0; k < 6; k++) red[wid][k] = s[k];
    __syncthreads();
    if (tid < 6) {
        float tot = 0.f;
        for (int w2 = 0; w2 < 8; w2++) tot += red[w2][tid];
        atomicAdd(&d_simstats[((tid >> 1) * 8 + g) * 2 + (tid & 1)], tot);
    }
}

__global__ void simfin_kernel(const float* __restrict__ gsim) {
    int ch = threadIdx.x;
    if (ch < 24) {
        double sum = d_simstats[ch * 2], sq = d_simstats[ch * 2 + 1];
        double mean = sum / NSS;
        double var = sq / NSS - mean * mean;
        d_acoef[ch] = gsim[ch] * rsqrtf((float)var + EPSV);
    }
}

// Attention pass 2: logits -> softmax -> sv/sve + out-BN stats.
__global__ __launch_bounds__(256) void attn2_kernel(const float* __restrict__ rel,
                                                    const float* __restrict__ fqr_p,
                                                    const float* __restrict__ fkr_p,
                                                    const float* __restrict__ fsv_p,
                                                    const float* __restrict__ fsve_p) {
    const int b = blockIdx.x >> 3, g = blockIdx.x & 7;
    __shared__ float qs[384], ks[384], vs[768];
    __shared__ float rq[8 * 96], rk[8 * 96], rv[16 * 96];
    __shared__ float S[48 * 49];
    const int tid = threadIdx.x;
    const float* qsrc = d_Pproj + (b * 256 + 192 + g * 8) * 48;
    const float* ksrc = d_Pproj + (b * 256 + g * 24) * 48;
    const float* vsrc = d_Pproj + (b * 256 + g * 24 + 8) * 48;
    for (int i = tid; i < 384; i += 256) { qs[i] = qsrc[i]; ks[i] = ksrc[i]; }
    for (int i = tid; i < 768; i += 256) vs[i] = vsrc[i];
    for (int idx = tid; idx < 760; idx += 256) {
        int c = idx / 95, t = idx - c * 95;
        rq[c * 96 + t] = rel[idx];
        rk[c * 96 + t] = rel[760 + idx];
    }
    for (int idx = tid; idx < 1520; idx += 256) {
        int c = idx / 95, t = idx - c * 95;
        rv[c * 96 + t] = rel[1520 + idx];
    }
    const float fqr = *fqr_p, fkr = *fkr_p;
    const float a0 = d_acoef[g];
    const float a1 = d_acoef[8 + g] * fqr;
    const float a2 = d_acoef[16 + g] * fkr;
    __syncthreads();

    for (int m = 0; m < 9; m++) {
        int idx = tid + m * 256;
        int i = idx / 48, j = idx - i * 48;
        int tq = i - j + 47, tk = j - i + 47;
        float qk = 0.f, qr = 0.f, kr = 0.f;
#pragma unroll
        for (int c = 0; c < 8; c++) {
            float qv = qs[c * 48 + i], kv = ks[c * 48 + j];
            qk += qv * kv;
            qr += qv * rq[c * 96 + tq];
            kr += kv * rk[c * 96 + tk];
        }
        S[i * 49 + j] = a0 * qk + a1 * qr + a2 * kr;
    }
    __syncthreads();

    // softmax over j; warp wid handles rows wid*6 .. wid*6+5
    const int wid = tid >> 5, lane = tid & 31;
    for (int rr = 0; rr < 6; rr++) {
        const int i = wid * 6 + rr;
        float x0 = S[i * 49 + lane];
        float x1 = (lane < 16) ? S[i * 49 + 32 + lane] : -1e30f;
        float mx = fmaxf(x0, x1);
#pragma unroll
        for (int off = 16; off; off >>= 1) mx = fmaxf(mx, __shfl_xor_sync(0xffffffffu, mx, off));
        float e0 = __expf(x0 - mx);
        float e1 = (lane < 16) ? __expf(x1 - mx) : 0.f;
        float ssum = e0 + e1;
#pragma unroll
        for (int off = 16; off; off >>= 1) ssum += __shfl_xor_sync(0xffffffffu, ssum, off);
        float inv = 1.f / ssum;
        S[i * 49 + lane] = e0 * inv;
        if (lane < 16) S[i * 49 + 32 + lane] = e1 * inv;
    }
    __syncthreads();

    const float fsv = *fsv_p, fsve = *fsve_p;
    const int c = tid >> 4, u = tid & 15;
    const int ch = g * 16 + c;
    float st[4] = {0.f, 0.f, 0.f, 0.f};
    for (int m2 = 0; m2 < 3; m2++) {
        const int i = u * 3 + m2;
        float av = 0.f, ae = 0.f;
        const float* srow = &S[i * 49];
        const float* vrow = &vs[c * 48];
        const float* rrow = &rv[c * 96 + i + 47];
#pragma unroll 8
        for (int j = 0; j < 48; j++) {
            float sij = srow[j];
            av += sij * vrow[j];
            ae += sij * rrow[-j];
        }
        av *= fsv; ae *= fsve;
        d_sv [(ch * BB + b) * 48 + i] = av;
        d_sve[(ch * BB + b) * 48 + i] = ae;
        st[0] += av; st[1] += av * av;
        st[2] += ae; st[3] += ae * ae;
    }
#pragma unroll
    for (int off = 8; off; off >>= 1)
#pragma unroll
        for (int k = 0; k < 4; k++) st[k] += __shfl_xor_sync(0xffffffffu, st[k], off);
    if (u == 0) {
#pragma unroll
        for (int k = 0; k < 4; k++) atomicAdd(&d_outstats[ch * 4 + k], st[k]);
    }
}

__global__ void outfin_kernel(const float* __restrict__ gout, const float* __restrict__ bout) {
    int ch = threadIdx.x;
    if (ch < 128) {
        double s1 = d_outstats[ch * 4 + 0], q1 = d_outstats[ch * 4 + 1];
        double s2 = d_outstats[ch * 4 + 2], q2 = d_outstats[ch * 4 + 3];
        double m1 = s1 / NSP, v1 = q1 / NSP - m1 * m1;
        double m2 = s2 / NSP, v2 = q2 / NSP - m2 * m2;
        float sc1 = gout[ch * 2 + 0] * rsqrtf((float)v1 + EPSV);
        float sc2 = gout[ch * 2 + 1] * rsqrtf((float)v2 + EPSV);
        d_outcoef[ch * 3 + 0] = sc1;
        d_outcoef[ch * 3 + 1] = sc2;
        d_outcoef[ch * 3 + 2] = bout[ch * 2] + bout[ch * 2 + 1]
                                - (float)m1 * sc1 - (float)m2 * sc2;
    }
}

// Normalize, sum (sv,sve) pair, transpose (b,h)->(h,b), write output [128][48][48][48].
__global__ __launch_bounds__(256) void writeout_kernel(float* __restrict__ out) {
    const int ch = blockIdx.x / 48, bt = blockIdx.x - (blockIdx.x / 48) * 48;
    const int b0 = bt * 48;
    __shared__ float tile[48 * 49];
    const float sc1 = d_outcoef[ch * 3 + 0];
    const float sc2 = d_outcoef[ch * 3 + 1];
    const float sh  = d_outcoef[ch * 3 + 2];
    const float* svp  = d_sv  + (ch * BB + b0) * 48;
    const float* svep = d_sve + (ch * BB + b0) * 48;
    for (int idx = threadIdx.x; idx < 2304; idx += 256) {
        int bl = idx / 48, i = idx - bl * 48;
        tile[i * 49 + bl] = sc1 * svp[bl * 48 + i] + sc2 * svep[bl * 48 + i] + sh;
    }
    __syncthreads();
    float* op = out + ch * 110592 + b0;
    for (int idx = threadIdx.x; idx < 2304; idx += 256) {
        int i = idx / 48, bl = idx - i * 48;
        op[i * 2304 + bl] = tile[i * 49 + bl];
    }
}

// ---------------- launch ----------------
extern "C" void kernel_launch(void* const* d_in, const int* in_sizes, int n_in,
                              void* d_out, int out_size) {
    const float* x    = (const float*)d_in[0];
    const float* Wkv  = (const float*)d_in[1];
    const float* Wq   = (const float*)d_in[2];
    const float* gkv  = (const float*)d_in[3];
    const float* bkv  = (const float*)d_in[4];
    const float* gq   = (const float*)d_in[5];
    const float* bq   = (const float*)d_in[6];
    const float* gsim = (const float*)d_in[7];
    // d_in[8] = b_sim: cancels inside softmax (constant over softmax axis)
    const float* gout = (const float*)d_in[9];
    const float* bout = (const float*)d_in[10];
    const float* rel  = (const float*)d_in[11];
    const float* fqr  = (const float*)d_in[12];
    const float* fkr  = (const float*)d_in[13];
    const float* fsv  = (const float*)d_in[14];
    const float* fsve = (const float*)d_in[15];
    // d_in[16] = flatten_index: analytic (i - j + K - 1), not needed

    zero_kernel<<<1, 512>>>();
    cov_kernel<<<288, 256>>>(x);
    fold_kernel<<<256, 64>>>(Wkv, Wq, gkv, bkv, gq, bq);
    proj_kernel<<<2304, 256>>>(x);
    attn1_kernel<<<BB * NG, 256>>>(rel, fqr, fkr);
    simfin_kernel<<<1, 32>>>(gsim);
    attn2_kernel<<<BB * NG, 256>>>(rel, fqr, fkr, fsv, fsve);
    outfin_kernel<<<1, 128>>>(gout, bout);
    writeout_kernel<<<128 * 48, 256>>>((float*)d_out);
}

// round 10
// speedup vs baseline: 1.3885x; 1.3885x over previous
#include <cuda_runtime.h>

// RelativeAxialAttention, GB300. Round 9: register-blocked proj GEMM,
// 3x3 register-tiled attention logits, sliding-window sv/sve.

#define KH   48
#define BB   2304
#define NC   64
#define NG   8
#define NDK  8
#define NDV  16
#define NSP  110592.0
#define NSS  5308416.0
#define EPSV 1e-5f

// ---------------- scratch ----------------
__device__ float d_S[64];
__device__ float d_P[64 * 64];
__device__ float d_Wt[64 * 256];
__device__ float d_biasF[256];
__device__ float d_Pproj[BB * 256 * KH];
__device__ float d_simstats[3 * NG * 2];
__device__ float d_acoef[3 * NG];
__device__ float d_sv [NG * NDV * BB * KH];
__device__ float d_sve[NG * NDV * BB * KH];
__device__ float d_outstats[128 * 4];
__device__ float d_outcoef[128 * 3];

// ---------------- kernels ----------------
__global__ void zero_kernel() {
    int t = threadIdx.x;
    if (t < 64) d_S[t] = 0.f;
    for (int i = t; i < 4096; i += 512) d_P[i] = 0.f;
    if (t < 48)  d_simstats[t] = 0.f;
    d_outstats[t] = 0.f;
}

__global__ __launch_bounds__(256) void cov_kernel(const float* __restrict__ x) {
    __shared__ float xs[64 * 97];
    const int tid = threadIdx.x;
    const int r = tid >> 4, cc = tid & 15;
    float acc[4][4];
#pragma unroll
    for (int i = 0; i < 4; i++)
#pragma unroll
        for (int j = 0; j < 4; j++) acc[i][j] = 0.f;
    float csum = 0.f;

    for (int t = blockIdx.x; t < 1152; t += gridDim.x) {
        const int p0 = t * 96;
        for (int idx = tid; idx < 64 * 96; idx += 256) {
            int ch = idx / 96, p = idx - ch * 96;
            xs[ch * 97 + p] = x[ch * 110592 + p0 + p];
        }
        __syncthreads();
        for (int p = 0; p < 96; p++) {
            float a0 = xs[(4 * r + 0) * 97 + p];
            float a1 = xs[(4 * r + 1) * 97 + p];
            float a2 = xs[(4 * r + 2) * 97 + p];
            float a3 = xs[(4 * r + 3) * 97 + p];
            float b0 = xs[(4 * cc + 0) * 97 + p];
            float b1 = xs[(4 * cc + 1) * 97 + p];
            float b2 = xs[(4 * cc + 2) * 97 + p];
            float b3 = xs[(4 * cc + 3) * 97 + p];
            acc[0][0] += a0 * b0; acc[0][1] += a0 * b1; acc[0][2] += a0 * b2; acc[0][3] += a0 * b3;
            acc[1][0] += a1 * b0; acc[1][1] += a1 * b1; acc[1][2] += a1 * b2; acc[1][3] += a1 * b3;
            acc[2][0] += a2 * b0; acc[2][1] += a2 * b1; acc[2][2] += a2 * b2; acc[2][3] += a2 * b3;
            acc[3][0] += a3 * b0; acc[3][1] += a3 * b1; acc[3][2] += a3 * b2; acc[3][3] += a3 * b3;
        }
        if (tid < 64) {
            float s = 0.f;
            for (int p = 0; p < 96; p++) s += xs[tid * 97 + p];
            csum += s;
        }
        __syncthreads();
    }
#pragma unroll
    for (int i = 0; i < 4; i++)
#pragma unroll
        for (int j = 0; j < 4; j++)
            atomicAdd(&d_P[(4 * r + i) * 64 + 4 * cc + j], acc[i][j]);
    if (tid < 64) atomicAdd(&d_S[tid], csum);
}

__global__ void fold_kernel(const float* __restrict__ Wkv, const float* __restrict__ Wq,
                            const float* __restrict__ gkv, const float* __restrict__ bkv,
                            const float* __restrict__ gq,  const float* __restrict__ bq) {
    int o = blockIdx.x, d = threadIdx.x;
    __shared__ float ws[64], red[64], red2[64];
    __shared__ float sscale;
    float gg, bb;
    const float* Wrow;
    if (o < 192) { Wrow = Wkv + o * 64;        gg = gkv[o];       bb = bkv[o]; }
    else         { Wrow = Wq + (o - 192) * 64; gg = gq[o - 192];  bb = bq[o - 192]; }
    ws[d] = Wrow[d];
    __syncthreads();
    float mu_d = d_S[d] * (float)(1.0 / NSP);
    float col = 0.f;
    for (int c = 0; c < 64; c++) col += ws[c] * d_P[c * 64 + d];
    red[d]  = ws[d] * col;
    red2[d] = ws[d] * mu_d;
    __syncthreads();
    for (int s = 32; s > 0; s >>= 1) {
        if (d < s) { red[d] += red[d + s]; red2[d] += red2[d + s]; }
        __syncthreads();
    }
    if (d == 0) {
        float Ey2  = red[0] * (float)(1.0 / NSP);
        float mean = red2[0];
        float var  = Ey2 - mean * mean;
        float scale = gg * rsqrtf(var + EPSV);
        sscale = scale;
        d_biasF[o] = bb - mean * scale;
    }
    __syncthreads();
    d_Wt[d * 256 + o] = ws[d] * sscale;
}

// Projection v2: register-blocked GEMM.
// Block tile: 64 outputs x (8 b x 12 h) positions. Thread: 4 o x 6 p.
__global__ __launch_bounds__(256) void proj2_kernel(const float* __restrict__ x) {
    const int bo   = blockIdx.x & 3;          // o block: o0 = bo*64
    const int pb   = blockIdx.x >> 2;         // 0..1151
    const int hb   = pb & 3;                  // h0 = hb*12
    const int bblk = pb >> 2;                 // b0 = bblk*8
    const int o0 = bo * 64, h0 = hb * 12, b0 = bblk * 8;

    __shared__ float Ws[64 * 64];             // [c][o_local]
    __shared__ float Xs[64 * 96];             // [c][bl*12+hl]
    const int tid = threadIdx.x;
    const int oq = tid & 15;                  // o_local base = oq*4
    const int pq = tid >> 4;                  // p base = pq*6

    for (int idx = tid; idx < 4096; idx += 256) {
        int c = idx >> 6, ol = idx & 63;
        Ws[idx] = d_Wt[c * 256 + o0 + ol];
    }
    for (int idx = tid; idx < 64 * 96; idx += 256) {
        int bl = idx & 7;
        int rest = idx >> 3;
        int hl = rest % 12;
        int c  = rest / 12;
        Xs[c * 96 + bl * 12 + hl] = x[c * 110592 + (h0 + hl) * 2304 + b0 + bl];
    }
    __syncthreads();

    float acc[4][6];
#pragma unroll
    for (int oi = 0; oi < 4; oi++) {
        float bias = d_biasF[o0 + oq * 4 + oi];
#pragma unroll
        for (int l = 0; l < 6; l++) acc[oi][l] = bias;
    }

#pragma unroll 16
    for (int c = 0; c < 64; c++) {
        float4 wv = *reinterpret_cast<const float4*>(&Ws[c * 64 + oq * 4]);
        float xv[6];
#pragma unroll
        for (int l = 0; l < 6; l++) xv[l] = Xs[c * 96 + pq * 6 + l];
#pragma unroll
        for (int l = 0; l < 6; l++) {
            acc[0][l] += wv.x * xv[l];
            acc[1][l] += wv.y * xv[l];
            acc[2][l] += wv.z * xv[l];
            acc[3][l] += wv.w * xv[l];
        }
    }

#pragma unroll
    for (int l = 0; l < 6; l++) {
        int p = pq * 6 + l;
        int bl = p / 12, hl = p - bl * 12;
        float* dst = &d_Pproj[((b0 + bl) * 256 + o0 + oq * 4) * 48 + h0 + hl];
        dst[0]   = acc[0][l];
        dst[48]  = acc[1][l];
        dst[96]  = acc[2][l];
        dst[144] = acc[3][l];
    }
}

// Attention pass 1: 3x3 register-tiled logits -> sim-BN stats.
__global__ __launch_bounds__(256) void attn1_kernel(const float* __restrict__ rel,
                                                    const float* __restrict__ fqr_p,
                                                    const float* __restrict__ fkr_p) {
    const int b = blockIdx.x >> 3, g = blockIdx.x & 7;
    __shared__ float qs[384], ks[384], rq[8 * 96], rk[8 * 96];
    __shared__ float red[8][6];
    const int tid = threadIdx.x;
    const float* qsrc = d_Pproj + (b * 256 + 192 + g * 8) * 48;
    const float* ksrc = d_Pproj + (b * 256 + g * 24) * 48;
    for (int i = tid; i < 384; i += 256) { qs[i] = qsrc[i]; ks[i] = ksrc[i]; }
    for (int idx = tid; idx < 760; idx += 256) {
        int c = idx / 95, t = idx - c * 95;
        rq[c * 96 + t] = rel[idx];
        rk[c * 96 + t] = rel[760 + idx];
    }
    const float fqr = *fqr_p, fkr = *fkr_p;
    __syncthreads();

    const int ti = tid >> 4, tj = tid & 15;
    const int i0 = ti * 3, j0 = tj * 3;
    float qk[3][3], qr[3][3], kr[3][3];
#pragma unroll
    for (int a = 0; a < 3; a++)
#pragma unroll
        for (int bcol = 0; bcol < 3; bcol++) { qk[a][bcol] = 0.f; qr[a][bcol] = 0.f; kr[a][bcol] = 0.f; }

#pragma unroll
    for (int c = 0; c < 8; c++) {
        float qv[3], kv[3], rqv[5], rkv[5];
#pragma unroll
        for (int d = 0; d < 3; d++) { qv[d] = qs[c * 48 + i0 + d]; kv[d] = ks[c * 48 + j0 + d]; }
        const int tq0 = i0 - j0 + 45, tk0 = j0 - i0 + 45;
#pragma unroll
        for (int e = 0; e < 5; e++) { rqv[e] = rq[c * 96 + tq0 + e]; rkv[e] = rk[c * 96 + tk0 + e]; }
#pragma unroll
        for (int di = 0; di < 3; di++)
#pragma unroll
            for (int dj = 0; dj < 3; dj++) {
                qk[di][dj] += qv[di] * kv[dj];
                qr[di][dj] += qv[di] * rqv[di - dj + 2];
                kr[di][dj] += kv[dj] * rkv[dj - di + 2];
            }
    }

    float s[6] = {0.f, 0.f, 0.f, 0.f, 0.f, 0.f};
#pragma unroll
    for (int di = 0; di < 3; di++)
#pragma unroll
        for (int dj = 0; dj < 3; dj++) {
            float a = qk[di][dj];
            float bq2 = qr[di][dj] * fqr;
            float cr = kr[di][dj] * fkr;
            s[0] += a;   s[1] += a * a;
            s[2] += bq2; s[3] += bq2 * bq2;
            s[4] += cr;  s[5] += cr * cr;
        }
#pragma unroll
    for (int off = 16; off; off >>= 1)
#pragma unroll
        for (int k = 0; k < 6; k++) s[k] += __shfl_xor_sync(0xffffffffu, s[k], off);
    const int wid = tid >> 5, lane = tid & 31;
    if (lane == 0)
#pragma unroll
        for (int k = 0; k < 6; k++) red[wid][k] = s[k];
    __syncthreads();
    if (tid < 6) {
        float tot = 0.f;
        for (int w2 = 0; w2 < 8; w2++) tot += red[w2][tid];
        atomicAdd(&d_simstats[((tid >> 1) * 8 + g) * 2 + (tid & 1)], tot);
    }
}

__global__ void simfin_kernel(const float* __restrict__ gsim) {
    int ch = threadIdx.x;
    if (ch < 24) {
        double sum = d_simstats[ch * 2], sq = d_simstats[ch * 2 + 1];
        double mean = sum / NSS;
        double var = sq / NSS - mean * mean;
        d_acoef[ch] = gsim[ch] * rsqrtf((float)var + EPSV);
    }
}

// Attention pass 2: tiled logits -> softmax -> sv/sve (sliding window) + stats.
__global__ __launch_bounds__(256) void attn2_kernel(const float* __restrict__ rel,
                                                    const float* __restrict__ fqr_p,
                                                    const float* __restrict__ fkr_p,
                                                    const float* __restrict__ fsv_p,
                                                    const float* __restrict__ fsve_p) {
    const int b = blockIdx.x >> 3, g = blockIdx.x & 7;
    __shared__ float qs[384], ks[384], vs[768];
    __shared__ float rq[8 * 96], rk[8 * 96], rv[16 * 96];
    __shared__ float S[48 * 49];
    const int tid = threadIdx.x;
    const float* qsrc = d_Pproj + (b * 256 + 192 + g * 8) * 48;
    const float* ksrc = d_Pproj + (b * 256 + g * 24) * 48;
    const float* vsrc = d_Pproj + (b * 256 + g * 24 + 8) * 48;
    for (int i = tid; i < 384; i += 256) { qs[i] = qsrc[i]; ks[i] = ksrc[i]; }
    for (int i = tid; i < 768; i += 256) vs[i] = vsrc[i];
    for (int idx = tid; idx < 760; idx += 256) {
        int c = idx / 95, t = idx - c * 95;
        rq[c * 96 + t] = rel[idx];
        rk[c * 96 + t] = rel[760 + idx];
    }
    for (int idx = tid; idx < 1520; idx += 256) {
        int c = idx / 95, t = idx - c * 95;
        rv[c * 96 + t] = rel[1520 + idx];
    }
    const float fqr = *fqr_p, fkr = *fkr_p;
    const float a0 = d_acoef[g];
    const float a1 = d_acoef[8 + g] * fqr;
    const float a2 = d_acoef[16 + g] * fkr;
    __syncthreads();

    {
        const int ti = tid >> 4, tj = tid & 15;
        const int i0 = ti * 3, j0 = tj * 3;
        float qk[3][3], qr[3][3], kr[3][3];
#pragma unroll
        for (int a = 0; a < 3; a++)
#pragma unroll
            for (int bcol = 0; bcol < 3; bcol++) { qk[a][bcol] = 0.f; qr[a][bcol] = 0.f; kr[a][bcol] = 0.f; }
#pragma unroll
        for (int c = 0; c < 8; c++) {
            float qv[3], kv[3], rqv[5], rkv[5];
#pragma unroll
            for (int d = 0; d < 3; d++) { qv[d] = qs[c * 48 + i0 + d]; kv[d] = ks[c * 48 + j0 + d]; }
            const int tq0 = i0 - j0 + 45, tk0 = j0 - i0 + 45;
#pragma unroll
            for (int e = 0; e < 5; e++) { rqv[e] = rq[c * 96 + tq0 + e]; rkv[e] = rk[c * 96 + tk0 + e]; }
#pragma unroll
            for (int di = 0; di < 3; di++)
#pragma unroll
                for (int dj = 0; dj < 3; dj++) {
                    qk[di][dj] += qv[di] * kv[dj];
                    qr[di][dj] += qv[di] * rqv[di - dj + 2];
                    kr[di][dj] += kv[dj] * rkv[dj - di + 2];
                }
        }
#pragma unroll
        for (int di = 0; di < 3; di++)
#pragma unroll
            for (int dj = 0; dj < 3; dj++)
                S[(i0 + di) * 49 + j0 + dj] = a0 * qk[di][dj] + a1 * qr[di][dj] + a2 * kr[di][dj];
    }
    __syncthreads();

    // softmax over j; warp wid handles rows wid*6 .. wid*6+5
    const int wid = tid >> 5, lane = tid & 31;
    for (int rr = 0; rr < 6; rr++) {
        const int i = wid * 6 + rr;
        float x0 = S[i * 49 + lane];
        float x1 = (lane < 16) ? S[i * 49 + 32 + lane] : -1e30f;
        float mx = fmaxf(x0, x1);
#pragma unroll
        for (int off = 16; off; off >>= 1) mx = fmaxf(mx, __shfl_xor_sync(0xffffffffu, mx, off));
        float e0 = __expf(x0 - mx);
        float e1 = (lane < 16) ? __expf(x1 - mx) : 0.f;
        float ssum = e0 + e1;
#pragma unroll
        for (int off = 16; off; off >>= 1) ssum += __shfl_xor_sync(0xffffffffu, ssum, off);
        float inv = 1.f / ssum;
        S[i * 49 + lane] = e0 * inv;
        if (lane < 16) S[i * 49 + 32 + lane] = e1 * inv;
    }
    __syncthreads();

    const float fsv = *fsv_p, fsve = *fsve_p;
    const int c = tid >> 4, u = tid & 15;
    const int ch = g * 16 + c;
    const int i0 = u * 3;

    // sliding window on rv: w[d] = rv[c][i0+d+47-j]
    float w0 = rv[c * 96 + i0 + 47];
    float w1 = rv[c * 96 + i0 + 48];
    float w2 = rv[c * 96 + i0 + 49];
    float av0 = 0.f, av1 = 0.f, av2 = 0.f;
    float ae0 = 0.f, ae1 = 0.f, ae2 = 0.f;
#pragma unroll 8
    for (int j = 0; j < 48; j++) {
        float vv = vs[c * 48 + j];
        float s0 = S[(i0 + 0) * 49 + j];
        float s1 = S[(i0 + 1) * 49 + j];
        float s2 = S[(i0 + 2) * 49 + j];
        av0 += s0 * vv; av1 += s1 * vv; av2 += s2 * vv;
        ae0 += s0 * w0; ae1 += s1 * w1; ae2 += s2 * w2;
        int nidx = i0 + 46 - j;
        nidx = nidx < 0 ? 0 : nidx;       // value unused at j=47
        w2 = w1; w1 = w0; w0 = rv[c * 96 + nidx];
    }
    av0 *= fsv; av1 *= fsv; av2 *= fsv;
    ae0 *= fsve; ae1 *= fsve; ae2 *= fsve;

    float* svp  = &d_sv [(ch * BB + b) * 48 + i0];
    float* svep = &d_sve[(ch * BB + b) * 48 + i0];
    svp[0] = av0;  svp[1] = av1;  svp[2] = av2;
    svep[0] = ae0; svep[1] = ae1; svep[2] = ae2;

    float st[4];
    st[0] = av0 + av1 + av2;
    st[1] = av0 * av0 + av1 * av1 + av2 * av2;
    st[2] = ae0 + ae1 + ae2;
    st[3] = ae0 * ae0 + ae1 * ae1 + ae2 * ae2;
#pragma unroll
    for (int off = 8; off; off >>= 1)
#pragma unroll
        for (int k = 0; k < 4; k++) st[k] += __shfl_xor_sync(0xffffffffu, st[k], off);
    if (u == 0) {
#pragma unroll
        for (int k = 0; k < 4; k++) atomicAdd(&d_outstats[ch * 4 + k], st[k]);
    }
}

__global__ void outfin_kernel(const float* __restrict__ gout, const float* __restrict__ bout) {
    int ch = threadIdx.x;
    if (ch < 128) {
        double s1 = d_outstats[ch * 4 + 0], q1 = d_outstats[ch * 4 + 1];
        double s2 = d_outstats[ch * 4 + 2], q2 = d_outstats[ch * 4 + 3];
        double m1 = s1 / NSP, v1 = q1 / NSP - m1 * m1;
        double m2 = s2 / NSP, v2 = q2 / NSP - m2 * m2;
        float sc1 = gout[ch * 2 + 0] * rsqrtf((float)v1 + EPSV);
        float sc2 = gout[ch * 2 + 1] * rsqrtf((float)v2 + EPSV);
        d_outcoef[ch * 3 + 0] = sc1;
        d_outcoef[ch * 3 + 1] = sc2;
        d_outcoef[ch * 3 + 2] = bout[ch * 2] + bout[ch * 2 + 1]
                                - (float)m1 * sc1 - (float)m2 * sc2;
    }
}

__global__ __launch_bounds__(256) void writeout_kernel(float* __restrict__ out) {
    const int ch = blockIdx.x / 48, bt = blockIdx.x - (blockIdx.x / 48) * 48;
    const int b0 = bt * 48;
    __shared__ float tile[48 * 49];
    const float sc1 = d_outcoef[ch * 3 + 0];
    const float sc2 = d_outcoef[ch * 3 + 1];
    const float sh  = d_outcoef[ch * 3 + 2];
    const float* svp  = d_sv  + (ch * BB + b0) * 48;
    const float* svep = d_sve + (ch * BB + b0) * 48;
    for (int idx = threadIdx.x; idx < 2304; idx += 256) {
        int bl = idx / 48, i = idx - bl * 48;
        tile[i * 49 + bl] = sc1 * svp[bl * 48 + i] + sc2 * svep[bl * 48 + i] + sh;
    }
    __syncthreads();
    float* op = out + ch * 110592 + b0;
    for (int idx = threadIdx.x; idx < 2304; idx += 256) {
        int i = idx / 48, bl = idx - i * 48;
        op[i * 2304 + bl] = tile[i * 49 + bl];
    }
}

// ---------------- launch ----------------
extern "C" void kernel_launch(void* const* d_in, const int* in_sizes, int n_in,
                              void* d_out, int out_size) {
    const float* x    = (const float*)d_in[0];
    const float* Wkv  = (const float*)d_in[1];
    const float* Wq   = (const float*)d_in[2];
    const float* gkv  = (const float*)d_in[3];
    const float* bkv  = (const float*)d_in[4];
    const float* gq   = (const float*)d_in[5];
    const float* bq   = (const float*)d_in[6];
    const float* gsim = (const float*)d_in[7];
    const float* gout = (const float*)d_in[9];
    const float* bout = (const float*)d_in[10];
    const float* rel  = (const float*)d_in[11];
    const float* fqr  = (const float*)d_in[12];
    const float* fkr  = (const float*)d_in[13];
    const float* fsv  = (const float*)d_in[14];
    const float* fsve = (const float*)d_in[15];

    zero_kernel<<<1, 512>>>();
    cov_kernel<<<288, 256>>>(x);
    fold_kernel<<<256, 64>>>(Wkv, Wq, gkv, bkv, gq, bq);
    proj2_kernel<<<4608, 256>>>(x);
    attn1_kernel<<<BB * NG, 256>>>(rel, fqr, fkr);
    simfin_kernel<<<1, 32>>>(gsim);
    attn2_kernel<<<BB * NG, 256>>>(rel, fqr, fkr, fsv, fsve);
    outfin_kernel<<<1, 128>>>(gout, bout);
    writeout_kernel<<<128 * 48, 256>>>((float*)d_out);
}

// round 11
// speedup vs baseline: 1.5336x; 1.1045x over previous
#include <cuda_runtime.h>

// RelativeAxialAttention, GB300. Round 10: float4 proj GEMM (proj3),
// closed-form Gram-based sim-BN stats (replaces brute-force attn1).

#define KH   48
#define BB   2304
#define NC   64
#define NG   8
#define NDK  8
#define NDV  16
#define NSP  110592.0
#define NSS  5308416.0
#define EPSV 1e-5f

// ---------------- scratch ----------------
__device__ float d_S[64];
__device__ float d_P[64 * 64];
__device__ __align__(16) float d_Wt[64 * 256];
__device__ __align__(16) float d_biasF[256];
__device__ __align__(16) float d_Pproj[BB * 256 * KH];
__device__ float d_simstats[3 * NG * 2];
__device__ float d_acoef[3 * NG];
__device__ float d_sv [NG * NDV * BB * KH];
__device__ float d_sve[NG * NDV * BB * KH];
__device__ float d_outstats[128 * 4];
__device__ float d_outcoef[128 * 3];
// sim-BN precomputed tables (b-independent)
__device__ float d_SRq[8 * 48], d_SRk[8 * 48];
__device__ float d_RRq[36 * 48], d_RRk[36 * 48];

// ---------------- kernels ----------------
__global__ void zero_kernel() {
    int t = threadIdx.x;
    if (t < 64) d_S[t] = 0.f;
    for (int i = t; i < 4096; i += 512) d_P[i] = 0.f;
    if (t < 48)  d_simstats[t] = 0.f;
    d_outstats[t] = 0.f;
}

__global__ __launch_bounds__(256) void cov_kernel(const float* __restrict__ x) {
    __shared__ float xs[64 * 97];
    const int tid = threadIdx.x;
    const int r = tid >> 4, cc = tid & 15;
    float acc[4][4];
#pragma unroll
    for (int i = 0; i < 4; i++)
#pragma unroll
        for (int j = 0; j < 4; j++) acc[i][j] = 0.f;
    float csum = 0.f;

    for (int t = blockIdx.x; t < 1152; t += gridDim.x) {
        const int p0 = t * 96;
        for (int idx = tid; idx < 64 * 96; idx += 256) {
            int ch = idx / 96, p = idx - ch * 96;
            xs[ch * 97 + p] = x[ch * 110592 + p0 + p];
        }
        __syncthreads();
        for (int p = 0; p < 96; p++) {
            float a0 = xs[(4 * r + 0) * 97 + p];
            float a1 = xs[(4 * r + 1) * 97 + p];
            float a2 = xs[(4 * r + 2) * 97 + p];
            float a3 = xs[(4 * r + 3) * 97 + p];
            float b0 = xs[(4 * cc + 0) * 97 + p];
            float b1 = xs[(4 * cc + 1) * 97 + p];
            float b2 = xs[(4 * cc + 2) * 97 + p];
            float b3 = xs[(4 * cc + 3) * 97 + p];
            acc[0][0] += a0 * b0; acc[0][1] += a0 * b1; acc[0][2] += a0 * b2; acc[0][3] += a0 * b3;
            acc[1][0] += a1 * b0; acc[1][1] += a1 * b1; acc[1][2] += a1 * b2; acc[1][3] += a1 * b3;
            acc[2][0] += a2 * b0; acc[2][1] += a2 * b1; acc[2][2] += a2 * b2; acc[2][3] += a2 * b3;
            acc[3][0] += a3 * b0; acc[3][1] += a3 * b1; acc[3][2] += a3 * b2; acc[3][3] += a3 * b3;
        }
        if (tid < 64) {
            float s = 0.f;
            for (int p = 0; p < 96; p++) s += xs[tid * 97 + p];
            csum += s;
        }
        __syncthreads();
    }
#pragma unroll
    for (int i = 0; i < 4; i++)
#pragma unroll
        for (int j = 0; j < 4; j++)
            atomicAdd(&d_P[(4 * r + i) * 64 + 4 * cc + j], acc[i][j]);
    if (tid < 64) atomicAdd(&d_S[tid], csum);
}

__global__ void fold_kernel(const float* __restrict__ Wkv, const float* __restrict__ Wq,
                            const float* __restrict__ gkv, const float* __restrict__ bkv,
                            const float* __restrict__ gq,  const float* __restrict__ bq) {
    int o = blockIdx.x, d = threadIdx.x;
    __shared__ float ws[64], red[64], red2[64];
    __shared__ float sscale;
    float gg, bb;
    const float* Wrow;
    if (o < 192) { Wrow = Wkv + o * 64;        gg = gkv[o];       bb = bkv[o]; }
    else         { Wrow = Wq + (o - 192) * 64; gg = gq[o - 192];  bb = bq[o - 192]; }
    ws[d] = Wrow[d];
    __syncthreads();
    float mu_d = d_S[d] * (float)(1.0 / NSP);
    float col = 0.f;
    for (int c = 0; c < 64; c++) col += ws[c] * d_P[c * 64 + d];
    red[d]  = ws[d] * col;
    red2[d] = ws[d] * mu_d;
    __syncthreads();
    for (int s = 32; s > 0; s >>= 1) {
        if (d < s) { red[d] += red[d + s]; red2[d] += red2[d + s]; }
        __syncthreads();
    }
    if (d == 0) {
        float Ey2  = red[0] * (float)(1.0 / NSP);
        float mean = red2[0];
        float var  = Ey2 - mean * mean;
        float scale = gg * rsqrtf(var + EPSV);
        sscale = scale;
        d_biasF[o] = bb - mean * scale;
    }
    __syncthreads();
    d_Wt[d * 256 + o] = ws[d] * sscale;
}

// Projection v3: float4 register-blocked GEMM.
// Block: 64 o x 128 p (8 b x 16 h). Thread: 4 o x 8 h (one b).
__global__ __launch_bounds__(256) void proj3_kernel(const float* __restrict__ x) {
    const int bo   = blockIdx.x & 3;
    const int rest = blockIdx.x >> 2;
    const int hb   = rest % 3;
    const int bblk = rest / 3;
    const int o0 = bo * 64, h0 = hb * 16, b0 = bblk * 8;

    __shared__ __align__(16) float Ws[64 * 64];   // [c][ol]
    __shared__ __align__(16) float Xs[64 * 128];  // [c][bl*16+hl]
    const int tid = threadIdx.x;

    const float4* wt4 = (const float4*)d_Wt;
    float4* ws4w = (float4*)Ws;
    for (int idx = tid; idx < 1024; idx += 256) {
        int c = idx >> 4, olq = idx & 15;
        ws4w[c * 16 + olq] = wt4[c * 64 + (o0 >> 2) + olq];
    }
    const float4* x4 = (const float4*)x;
    for (int idx = tid; idx < 2048; idx += 256) {
        int bq = idx & 1;
        int hl = (idx >> 1) & 15;
        int c  = idx >> 5;
        float4 v = x4[c * 27648 + (h0 + hl) * 576 + (b0 >> 2) + bq];
        int pb = bq * 4;
        Xs[c * 128 + (pb + 0) * 16 + hl] = v.x;
        Xs[c * 128 + (pb + 1) * 16 + hl] = v.y;
        Xs[c * 128 + (pb + 2) * 16 + hl] = v.z;
        Xs[c * 128 + (pb + 3) * 16 + hl] = v.w;
    }
    __syncthreads();

    const int oq = tid & 15;
    const int pq = tid >> 4;
    const int bl = pq >> 1;
    const int hh = (pq & 1) * 8;

    float acc[4][8];
    {
        const float4 b4 = *(const float4*)&d_biasF[o0 + oq * 4];
        float bb[4] = {b4.x, b4.y, b4.z, b4.w};
#pragma unroll
        for (int oi = 0; oi < 4; oi++)
#pragma unroll
            for (int hl = 0; hl < 8; hl++) acc[oi][hl] = bb[oi];
    }

    const float4* ws4 = (const float4*)Ws;
    const float4* xs4 = (const float4*)Xs;
    const int xbase = bl * 4 + (hh >> 2);
#pragma unroll 8
    for (int c = 0; c < 64; c++) {
        float4 wv = ws4[c * 16 + oq];
        float4 xa = xs4[c * 32 + xbase];
        float4 xb = xs4[c * 32 + xbase + 1];
        float xv[8] = {xa.x, xa.y, xa.z, xa.w, xb.x, xb.y, xb.z, xb.w};
        float wf[4] = {wv.x, wv.y, wv.z, wv.w};
#pragma unroll
        for (int oi = 0; oi < 4; oi++)
#pragma unroll
            for (int hl = 0; hl < 8; hl++)
                acc[oi][hl] = fmaf(wf[oi], xv[hl], acc[oi][hl]);
    }

    const int b = b0 + bl;
#pragma unroll
    for (int oi = 0; oi < 4; oi++) {
        float* dst = &d_Pproj[(b * 256 + o0 + oq * 4 + oi) * 48 + h0 + hh];
        *(float4*)(dst)     = make_float4(acc[oi][0], acc[oi][1], acc[oi][2], acc[oi][3]);
        *(float4*)(dst + 4) = make_float4(acc[oi][4], acc[oi][5], acc[oi][6], acc[oi][7]);
    }
}

// Precompute b-independent rel tables: SR (sliding sums), RR (sliding pair dot).
__global__ void simpre_kernel(const float* __restrict__ rel) {
    int t = threadIdx.x;
    if (t < 72) {
        int isk = t >= 36 ? 1 : 0;
        int p = t - 36 * isk;
        int c0 = 0, rem = p;
        while (rem >= 8 - c0) { rem -= 8 - c0; c0++; }
        int c1 = c0 + rem;
        const float* r0 = rel + (isk * 8 + c0) * 95;
        const float* r1 = rel + (isk * 8 + c1) * 95;
        float* dst = isk ? d_RRk : d_RRq;
        float acc = 0.f;
        for (int tt = 0; tt < 48; tt++) acc += r0[tt] * r1[tt];
        dst[p * 48] = acc;
        for (int i = 1; i < 48; i++) {
            acc += r0[i + 47] * r1[i + 47] - r0[i - 1] * r1[i - 1];
            dst[p * 48 + i] = acc;
        }
    } else if (t < 88) {
        int isk = (t - 72) >= 8 ? 1 : 0;
        int c = (t - 72) - 8 * isk;
        const float* r0 = rel + (isk * 8 + c) * 95;
        float* dst = isk ? d_SRk : d_SRq;
        float acc = 0.f;
        for (int tt = 0; tt < 48; tt++) acc += r0[tt];
        dst[c * 48] = acc;
        for (int i = 1; i < 48; i++) {
            acc += r0[i + 47] - r0[i - 1];
            dst[c * 48 + i] = acc;
        }
    }
}

// sim-BN stats via Gram factorization. Block per b, warp per g.
__global__ __launch_bounds__(256) void attn1g_kernel() {
    const int b = blockIdx.x;
    __shared__ float qs[64 * 49], ks[64 * 49];
    __shared__ float RRq_s[36 * 49], RRk_s[36 * 49];
    __shared__ float SRq_s[8 * 48], SRk_s[8 * 48];
    __shared__ float shv[8][4][8];   // [g][qsum,ksum,A,B][c]
    const int tid = threadIdx.x;

    const float* qbase = d_Pproj + (b * 256 + 192) * 48;
    for (int idx = tid; idx < 3072; idx += 256) {
        int o = idx / 48, i = idx - o * 48;
        qs[o * 49 + i] = qbase[idx];
    }
    for (int idx = tid; idx < 3072; idx += 256) {
        int g = idx / 384, r = idx - g * 384, c = r / 48, i = r - c * 48;
        ks[(g * 8 + c) * 49 + i] = d_Pproj[(b * 256 + g * 24 + c) * 48 + i];
    }
    for (int idx = tid; idx < 36 * 48; idx += 256) {
        int p = idx / 48, i = idx - p * 48;
        RRq_s[p * 49 + i] = d_RRq[idx];
        RRk_s[p * 49 + i] = d_RRk[idx];
    }
    for (int idx = tid; idx < 8 * 48; idx += 256) {
        SRq_s[idx] = d_SRq[idx];
        SRk_s[idx] = d_SRk[idx];
    }
    __syncthreads();

    const int g = tid >> 5, l = tid & 31;
    float pqk2 = 0.f, pqr2 = 0.f, pkr2 = 0.f;
    for (int p = l; p < 36; p += 32) {
        int c0 = 0, rem = p;
        while (rem >= 8 - c0) { rem -= 8 - c0; c0++; }
        int c1 = c0 + rem;
        float mult = (c0 == c1) ? 1.f : 2.f;
        const float* q0 = &qs[(g * 8 + c0) * 49];
        const float* q1 = &qs[(g * 8 + c1) * 49];
        const float* k0 = &ks[(g * 8 + c0) * 49];
        const float* k1 = &ks[(g * 8 + c1) * 49];
        const float* rrq = &RRq_s[p * 49];
        const float* rrk = &RRk_s[p * 49];
        float gq = 0.f, gk = 0.f, wq = 0.f, wk = 0.f;
#pragma unroll 8
        for (int i = 0; i < 48; i++) {
            float qq = q0[i] * q1[i];
            gq += qq; wq = fmaf(qq, rrq[i], wq);
            float kk = k0[i] * k1[i];
            gk += kk; wk = fmaf(kk, rrk[i], wk);
        }
        pqk2 += mult * gq * gk;
        pqr2 += mult * wq;
        pkr2 += mult * wk;
    }
    if (l < 8) {
        int c = l;
        const float* q0 = &qs[(g * 8 + c) * 49];
        const float* sr = &SRq_s[c * 48];
        float s = 0.f, a = 0.f;
        for (int i = 0; i < 48; i++) { s += q0[i]; a = fmaf(q0[i], sr[i], a); }
        shv[g][0][c] = s; shv[g][2][c] = a;
    } else if (l < 16) {
        int c = l - 8;
        const float* k0 = &ks[(g * 8 + c) * 49];
        const float* sr = &SRk_s[c * 48];
        float s = 0.f, a = 0.f;
        for (int i = 0; i < 48; i++) { s += k0[i]; a = fmaf(k0[i], sr[i], a); }
        shv[g][1][c] = s; shv[g][3][c] = a;
    }
    __syncwarp();
#pragma unroll
    for (int off = 16; off; off >>= 1) {
        pqk2 += __shfl_xor_sync(0xffffffffu, pqk2, off);
        pqr2 += __shfl_xor_sync(0xffffffffu, pqr2, off);
        pkr2 += __shfl_xor_sync(0xffffffffu, pkr2, off);
    }
    if (l == 0) {
        float sqk = 0.f, sqr = 0.f, skr = 0.f;
#pragma unroll
        for (int c = 0; c < 8; c++) {
            sqk = fmaf(shv[g][0][c], shv[g][1][c], sqk);
            sqr += shv[g][2][c];
            skr += shv[g][3][c];
        }
        atomicAdd(&d_simstats[(0  + g) * 2 + 0], sqk);
        atomicAdd(&d_simstats[(0  + g) * 2 + 1], pqk2);
        atomicAdd(&d_simstats[(8  + g) * 2 + 0], sqr);
        atomicAdd(&d_simstats[(8  + g) * 2 + 1], pqr2);
        atomicAdd(&d_simstats[(16 + g) * 2 + 0], skr);
        atomicAdd(&d_simstats[(16 + g) * 2 + 1], pkr2);
    }
}

__global__ void simfin_kernel(const float* __restrict__ gsim,
                              const float* __restrict__ fqr_p,
                              const float* __restrict__ fkr_p) {
    int ch = threadIdx.x;
    if (ch < 24) {
        double f = 1.0;
        if (ch >= 8 && ch < 16) f = (double)*fqr_p;
        else if (ch >= 16)      f = (double)*fkr_p;
        double sum = (double)d_simstats[ch * 2] * f;
        double sq  = (double)d_simstats[ch * 2 + 1] * f * f;
        double mean = sum / NSS;
        double var  = sq / NSS - mean * mean;
        d_acoef[ch] = gsim[ch] * rsqrtf((float)var + EPSV);
    }
}

// Attention pass 2: tiled logits -> softmax -> sv/sve (sliding window) + stats.
__global__ __launch_bounds__(256) void attn2_kernel(const float* __restrict__ rel,
                                                    const float* __restrict__ fqr_p,
                                                    const float* __restrict__ fkr_p,
                                                    const float* __restrict__ fsv_p,
                                                    const float* __restrict__ fsve_p) {
    const int b = blockIdx.x >> 3, g = blockIdx.x & 7;
    __shared__ float qs[384], ks[384], vs[768];
    __shared__ float rq[8 * 96], rk[8 * 96], rv[16 * 96];
    __shared__ float S[48 * 49];
    const int tid = threadIdx.x;
    const float* qsrc = d_Pproj + (b * 256 + 192 + g * 8) * 48;
    const float* ksrc = d_Pproj + (b * 256 + g * 24) * 48;
    const float* vsrc = d_Pproj + (b * 256 + g * 24 + 8) * 48;
    for (int i = tid; i < 384; i += 256) { qs[i] = qsrc[i]; ks[i] = ksrc[i]; }
    for (int i = tid; i < 768; i += 256) vs[i] = vsrc[i];
    for (int idx = tid; idx < 760; idx += 256) {
        int c = idx / 95, t = idx - c * 95;
        rq[c * 96 + t] = rel[idx];
        rk[c * 96 + t] = rel[760 + idx];
    }
    for (int idx = tid; idx < 1520; idx += 256) {
        int c = idx / 95, t = idx - c * 95;
        rv[c * 96 + t] = rel[1520 + idx];
    }
    const float fqr = *fqr_p, fkr = *fkr_p;
    const float a0 = d_acoef[g];
    const float a1 = d_acoef[8 + g] * fqr;
    const float a2 = d_acoef[16 + g] * fkr;
    __syncthreads();

    {
        const int ti = tid >> 4, tj = tid & 15;
        const int i0 = ti * 3, j0 = tj * 3;
        float qk[3][3], qr[3][3], kr[3][3];
#pragma unroll
        for (int a = 0; a < 3; a++)
#pragma unroll
            for (int bcol = 0; bcol < 3; bcol++) { qk[a][bcol] = 0.f; qr[a][bcol] = 0.f; kr[a][bcol] = 0.f; }
#pragma unroll
        for (int c = 0; c < 8; c++) {
            float qv[3], kv[3], rqv[5], rkv[5];
#pragma unroll
            for (int d = 0; d < 3; d++) { qv[d] = qs[c * 48 + i0 + d]; kv[d] = ks[c * 48 + j0 + d]; }
            const int tq0 = i0 - j0 + 45, tk0 = j0 - i0 + 45;
#pragma unroll
            for (int e = 0; e < 5; e++) { rqv[e] = rq[c * 96 + tq0 + e]; rkv[e] = rk[c * 96 + tk0 + e]; }
#pragma unroll
            for (int di = 0; di < 3; di++)
#pragma unroll
                for (int dj = 0; dj < 3; dj++) {
                    qk[di][dj] += qv[di] * kv[dj];
                    qr[di][dj] += qv[di] * rqv[di - dj + 2];
                    kr[di][dj] += kv[dj] * rkv[dj - di + 2];
                }
        }
#pragma unroll
        for (int di = 0; di < 3; di++)
#pragma unroll
            for (int dj = 0; dj < 3; dj++)
                S[(i0 + di) * 49 + j0 + dj] = a0 * qk[di][dj] + a1 * qr[di][dj] + a2 * kr[di][dj];
    }
    __syncthreads();

    const int wid = tid >> 5, lane = tid & 31;
    for (int rr = 0; rr < 6; rr++) {
        const int i = wid * 6 + rr;
        float x0 = S[i * 49 + lane];
        float x1 = (lane < 16) ? S[i * 49 + 32 + lane] : -1e30f;
        float mx = fmaxf(x0, x1);
#pragma unroll
        for (int off = 16; off; off >>= 1) mx = fmaxf(mx, __shfl_xor_sync(0xffffffffu, mx, off));
        float e0 = __expf(x0 - mx);
        float e1 = (lane < 16) ? __expf(x1 - mx) : 0.f;
        float ssum = e0 + e1;
#pragma unroll
        for (int off = 16; off; off >>= 1) ssum += __shfl_xor_sync(0xffffffffu, ssum, off);
        float inv = 1.f / ssum;
        S[i * 49 + lane] = e0 * inv;
        if (lane < 16) S[i * 49 + 32 + lane] = e1 * inv;
    }
    __syncthreads();

    const float fsv = *fsv_p, fsve = *fsve_p;
    const int c = tid >> 4, u = tid & 15;
    const int ch = g * 16 + c;
    const int i0 = u * 3;

    float w0 = rv[c * 96 + i0 + 47];
    float w1 = rv[c * 96 + i0 + 48];
    float w2 = rv[c * 96 + i0 + 49];
    float av0 = 0.f, av1 = 0.f, av2 = 0.f;
    float ae0 = 0.f, ae1 = 0.f, ae2 = 0.f;
#pragma unroll 8
    for (int j = 0; j < 48; j++) {
        float vv = vs[c * 48 + j];
        float s0 = S[(i0 + 0) * 49 + j];
        float s1 = S[(i0 + 1) * 49 + j];
        float s2 = S[(i0 + 2) * 49 + j];
        av0 += s0 * vv; av1 += s1 * vv; av2 += s2 * vv;
        ae0 += s0 * w0; ae1 += s1 * w1; ae2 += s2 * w2;
        int nidx = i0 + 46 - j;
        nidx = nidx < 0 ? 0 : nidx;
        w2 = w1; w1 = w0; w0 = rv[c * 96 + nidx];
    }
    av0 *= fsv; av1 *= fsv; av2 *= fsv;
    ae0 *= fsve; ae1 *= fsve; ae2 *= fsve;

    float* svp  = &d_sv [(ch * BB + b) * 48 + i0];
    float* svep = &d_sve[(ch * BB + b) * 48 + i0];
    svp[0] = av0;  svp[1] = av1;  svp[2] = av2;
    svep[0] = ae0; svep[1] = ae1; svep[2] = ae2;

    float st[4];
    st[0] = av0 + av1 + av2;
    st[1] = av0 * av0 + av1 * av1 + av2 * av2;
    st[2] = ae0 + ae1 + ae2;
    st[3] = ae0 * ae0 + ae1 * ae1 + ae2 * ae2;
#pragma unroll
    for (int off = 8; off; off >>= 1)
#pragma unroll
        for (int k = 0; k < 4; k++) st[k] += __shfl_xor_sync(0xffffffffu, st[k], off);
    if (u == 0) {
#pragma unroll
        for (int k = 0; k < 4; k++) atomicAdd(&d_outstats[ch * 4 + k], st[k]);
    }
}

__global__ void outfin_kernel(const float* __restrict__ gout, const float* __restrict__ bout) {
    int ch = threadIdx.x;
    if (ch < 128) {
        double s1 = d_outstats[ch * 4 + 0], q1 = d_outstats[ch * 4 + 1];
        double s2 = d_outstats[ch * 4 + 2], q2 = d_outstats[ch * 4 + 3];
        double m1 = s1 / NSP, v1 = q1 / NSP - m1 * m1;
        double m2 = s2 / NSP, v2 = q2 / NSP - m2 * m2;
        float sc1 = gout[ch * 2 + 0] * rsqrtf((float)v1 + EPSV);
        float sc2 = gout[ch * 2 + 1] * rsqrtf((float)v2 + EPSV);
        d_outcoef[ch * 3 + 0] = sc1;
        d_outcoef[ch * 3 + 1] = sc2;
        d_outcoef[ch * 3 + 2] = bout[ch * 2] + bout[ch * 2 + 1]
                                - (float)m1 * sc1 - (float)m2 * sc2;
    }
}

__global__ __launch_bounds__(256) void writeout_kernel(float* __restrict__ out) {
    const int ch = blockIdx.x / 48, bt = blockIdx.x - (blockIdx.x / 48) * 48;
    const int b0 = bt * 48;
    __shared__ float tile[48 * 49];
    const float sc1 = d_outcoef[ch * 3 + 0];
    const float sc2 = d_outcoef[ch * 3 + 1];
    const float sh  = d_outcoef[ch * 3 + 2];
    const float* svp  = d_sv  + (ch * BB + b0) * 48;
    const float* svep = d_sve + (ch * BB + b0) * 48;
    for (int idx = threadIdx.x; idx < 2304; idx += 256) {
        int bl = idx / 48, i = idx - bl * 48;
        tile[i * 49 + bl] = sc1 * svp[bl * 48 + i] + sc2 * svep[bl * 48 + i] + sh;
    }
    __syncthreads();
    float* op = out + ch * 110592 + b0;
    for (int idx = threadIdx.x; idx < 2304; idx += 256) {
        int i = idx / 48, bl = idx - i * 48;
        op[i * 2304 + bl] = tile[i * 49 + bl];
    }
}

// ---------------- launch ----------------
extern "C" void kernel_launch(void* const* d_in, const int* in_sizes, int n_in,
                              void* d_out, int out_size) {
    const float* x    = (const float*)d_in[0];
    const float* Wkv  = (const float*)d_in[1];
    const float* Wq   = (const float*)d_in[2];
    const float* gkv  = (const float*)d_in[3];
    const float* bkv  = (const float*)d_in[4];
    const float* gq   = (const float*)d_in[5];
    const float* bq   = (const float*)d_in[6];
    const float* gsim = (const float*)d_in[7];
    const float* gout = (const float*)d_in[9];
    const float* bout = (const float*)d_in[10];
    const float* rel  = (const float*)d_in[11];
    const float* fqr  = (const float*)d_in[12];
    const float* fkr  = (const float*)d_in[13];
    const float* fsv  = (const float*)d_in[14];
    const float* fsve = (const float*)d_in[15];

    zero_kernel<<<1, 512>>>();
    simpre_kernel<<<1, 128>>>(rel);
    cov_kernel<<<288, 256>>>(x);
    fold_kernel<<<256, 64>>>(Wkv, Wq, gkv, bkv, gq, bq);
    proj3_kernel<<<3456, 256>>>(x);
    attn1g_kernel<<<BB, 256>>>();
    simfin_kernel<<<1, 32>>>(gsim, fqr, fkr);
    attn2_kernel<<<BB * NG, 256>>>(rel, fqr, fkr, fsv, fsve);
    outfin_kernel<<<1, 128>>>(gout, bout);
    writeout_kernel<<<128 * 48, 256>>>((float*)d_out);
}